// round 1
// baseline (speedup 1.0000x reference)
#include <cuda_runtime.h>

#define Nn 50000
#define Ee 600000
#define Hh 128
#define EDd 16
#define Bb 256
#define Ll 5

// gemm epilogue mode bits
#define M_RELU 1
#define M_VN   2
#define M_RES  4
#define M_DIVC 8

// ---------------- device scratch (no allocation allowed) ----------------
__device__ float g_h[Nn * Hh];
__device__ float g_agg[Nn * Hh];
__device__ float g_x[Nn * Hh];
__device__ float g_sea[Nn * EDd];   // segment_sum(edge_attr, dst) -- layer invariant
__device__ float g_deg[Nn];         // in-degree (float)           -- layer invariant
__device__ float g_counts[Bb];      // nodes per graph             -- layer invariant
__device__ float g_vn[Bb * Hh];
__device__ float g_p1[Bb * Hh];
__device__ float g_pooled[Bb * Hh];

typedef unsigned long long u64;

// ---------------- f32x2 packed math (Blackwell FFMA2 pipe) ----------------
__device__ __forceinline__ u64 pack2(float x) {
    u64 d; asm("mov.b64 %0, {%1, %1};" : "=l"(d) : "f"(x)); return d;
}
__device__ __forceinline__ u64 fma2(u64 a, u64 b, u64 c) {
    u64 d; asm("fma.rn.f32x2 %0, %1, %2, %3;" : "=l"(d) : "l"(a), "l"(b), "l"(c)); return d;
}
__device__ __forceinline__ void unpack2(u64 v, float& lo, float& hi) {
    asm("mov.b64 {%0, %1}, %2;" : "=f"(lo), "=f"(hi) : "l"(v));
}
// vectorized fp32 reduction (sm_90+)
__device__ __forceinline__ void red4(float* p, float4 v) {
    asm volatile("red.global.add.v4.f32 [%0], {%1, %2, %3, %4};"
                 :: "l"(p), "f"(v.x), "f"(v.y), "f"(v.z), "f"(v.w) : "memory");
}

// ---------------- fused GEMM: C[M,128] = epilogue(A[M,128] @ W[128,128] + b) ----------------
// 64-row tiles, full K=128 and full N=128 resident in smem.
// 256 threads, each computes 4 rows x 8 cols via packed f32x2 FMAs.
__global__ void __launch_bounds__(256) gemm128(
    const float* __restrict__ A, const float* __restrict__ W,
    const float* __restrict__ bias, float* __restrict__ C, int M, int mode,
    const float* __restrict__ vn, const int* __restrict__ batch,
    const float* __restrict__ resid, const float* __restrict__ counts)
{
    extern __shared__ float sm[];
    float* As = sm;                 // 64*128 floats  (32 KB)
    float* Ws = sm + 64 * 128;      // 128*128 floats (64 KB)
    float* bs = sm + 64 * 128 + 128 * 128;  // 128 floats

    const int tid  = threadIdx.x;
    const int row0 = blockIdx.x * 64;

    // load W (row-major [k][n]) into smem
    const float4* W4  = (const float4*)W;
    float4*       Ws4 = (float4*)Ws;
#pragma unroll
    for (int i = 0; i < 16; i++) Ws4[tid + i * 256] = W4[tid + i * 256];
    if (tid < 128) bs[tid] = bias[tid];

    // load A tile (optionally scaled by 1/counts per row)
    const float4* A4  = (const float4*)A;
    float4*       As4 = (float4*)As;
#pragma unroll
    for (int i = 0; i < 8; i++) {
        int fidx = tid + i * 256;          // float4 index in tile: 0..2047
        int r = fidx >> 5, kq = fidx & 31;
        int gr = row0 + r;
        float4 v = make_float4(0.f, 0.f, 0.f, 0.f);
        if (gr < M) {
            v = A4[gr * 32 + kq];
            if (mode & M_DIVC) {
                float rc = 1.0f / fmaxf(counts[gr], 1.0f);
                v.x *= rc; v.y *= rc; v.z *= rc; v.w *= rc;
            }
        }
        As4[fidx] = v;
    }
    __syncthreads();

    const int tr = tid >> 4;   // 0..15 -> rows tr*4..tr*4+3
    const int tc = tid & 15;   // 0..15 -> cols tc*8..tc*8+7

    u64 acc[4][4];
#pragma unroll
    for (int r = 0; r < 4; r++)
#pragma unroll
        for (int j = 0; j < 4; j++) acc[r][j] = 0ull;

#pragma unroll 2
    for (int k0 = 0; k0 < 128; k0 += 4) {
        float4 av[4];
#pragma unroll
        for (int r = 0; r < 4; r++) av[r] = As4[(tr * 4 + r) * 32 + (k0 >> 2)];
#pragma unroll
        for (int kk = 0; kk < 4; kk++) {
            const ulonglong2* wp = (const ulonglong2*)(Ws + (k0 + kk) * 128 + tc * 8);
            ulonglong2 w01 = wp[0], w23 = wp[1];
            u64 wv0 = w01.x, wv1 = w01.y, wv2 = w23.x, wv3 = w23.y;
#pragma unroll
            for (int r = 0; r < 4; r++) {
                float a = (kk == 0) ? av[r].x : (kk == 1) ? av[r].y
                        : (kk == 2) ? av[r].z : av[r].w;
                u64 a2 = pack2(a);
                acc[r][0] = fma2(a2, wv0, acc[r][0]);
                acc[r][1] = fma2(a2, wv1, acc[r][1]);
                acc[r][2] = fma2(a2, wv2, acc[r][2]);
                acc[r][3] = fma2(a2, wv3, acc[r][3]);
            }
        }
    }

#pragma unroll
    for (int r = 0; r < 4; r++) {
        int gr = row0 + tr * 4 + r;
        if (gr >= M) continue;
        float o[8];
#pragma unroll
        for (int j = 0; j < 4; j++) unpack2(acc[r][j], o[2 * j], o[2 * j + 1]);
        const float* vrow = (mode & M_VN) ? (vn + (size_t)batch[gr] * 128) : (const float*)0;
#pragma unroll
        for (int c = 0; c < 8; c++) {
            int col = tc * 8 + c;
            float val = o[c] + bs[col];
            if (mode & M_VN)   val += vrow[col];
            if (mode & M_RELU) val = fmaxf(val, 0.0f);
            if (mode & M_RES)  val += resid[(size_t)gr * 128 + col];
            o[c] = val;
        }
        float4* Cp = (float4*)(C + (size_t)gr * 128 + tc * 8);
        Cp[0] = make_float4(o[0], o[1], o[2], o[3]);
        Cp[1] = make_float4(o[4], o[5], o[6], o[7]);
    }
}

// ---------------- layer-invariant precompute ----------------
__global__ void counts_kernel(const int* __restrict__ batch) {
    int n = blockIdx.x * 256 + threadIdx.x;
    if (n < Nn) atomicAdd(&g_counts[batch[n]], 1.0f);
}

__global__ void sea_deg_kernel(const float* __restrict__ ea, const int* __restrict__ ei) {
    int gid = blockIdx.x * 256 + threadIdx.x;
    int e = gid >> 2, q = gid & 3;          // 4 threads per edge (16 floats)
    if (e >= Ee) return;
    int dst = ei[Ee + e];
    float4 v = ((const float4*)ea)[e * 4 + q];
    red4(&g_sea[dst * 16 + q * 4], v);
    if (q == 0) atomicAdd(&g_deg[dst], 1.0f);
}

__global__ void vn_init_kernel(const float* __restrict__ vi) {
    int i = blockIdx.x * 256 + threadIdx.x;
    if (i < Bb * Hh) g_vn[i] = vi[i & 127];
}

// ---------------- agg = sea @ eW + deg (x) eb   (tiny [N,16]x[16,128] GEMM) ----------------
__global__ void agg_init_kernel(const float* __restrict__ eW, const float* __restrict__ eb) {
    __shared__ float ws[EDd * Hh];
    __shared__ float ebs[Hh];
    __shared__ float srow[2][EDd];
    int tid = threadIdx.x;
    for (int i = tid; i < EDd * Hh; i += 256) ws[i] = eW[i];
    if (tid < Hh) ebs[tid] = eb[tid];
    if (tid < 2 * EDd) {
        int rr = tid >> 4, j = tid & 15;
        int gr = blockIdx.x * 2 + rr;
        srow[rr][j] = (gr < Nn) ? g_sea[gr * 16 + j] : 0.f;
    }
    __syncthreads();
    int row = blockIdx.x * 2 + (tid >> 7);
    int c = tid & 127;
    if (row < Nn) {
        float acc = g_deg[row] * ebs[c];
#pragma unroll
        for (int j = 0; j < 16; j++) acc = fmaf(srow[tid >> 7][j], ws[j * 128 + c], acc);
        g_agg[row * 128 + c] = acc;
    }
}

// ---------------- agg[dst] += h[src]   (warp per edge, vector red) ----------------
__global__ void scatter_kernel(const int* __restrict__ ei) {
    int gid = blockIdx.x * 256 + threadIdx.x;
    int e = gid >> 5, q = gid & 31;
    if (e >= Ee) return;
    int src = ei[e], dst = ei[Ee + e];
    float4 v = ((const float4*)g_h)[src * 32 + q];
    red4(&g_agg[dst * 128 + q * 4], v);
}

// ---------------- pooled[batch[n]] += xsrc[n]  (warp per node) ----------------
__global__ void pool_kernel(const float* __restrict__ xsrc, const int* __restrict__ batch) {
    int gid = blockIdx.x * 256 + threadIdx.x;
    int n = gid >> 5, q = gid & 31;
    if (n >= Nn) return;
    int b = batch[n];
    float4 v = ((const float4*)xsrc)[n * 32 + q];
    red4(&g_pooled[b * 128 + q * 4], v);
}

// ---------------- launch ----------------
extern "C" void kernel_launch(void* const* d_in, const int* in_sizes, int n_in,
                              void* d_out, int out_size) {
    const float* x         = (const float*)d_in[0];
    const float* edge_attr = (const float*)d_in[1];
    const float* node_W    = (const float*)d_in[2];
    const float* node_b    = (const float*)d_in[3];
    const float* edge_W    = (const float*)d_in[4];
    const float* edge_b    = (const float*)d_in[5];
    const float* mlp1_W    = (const float*)d_in[6];
    const float* mlp1_b    = (const float*)d_in[7];
    const float* mlp2_W    = (const float*)d_in[8];
    const float* mlp2_b    = (const float*)d_in[9];
    const float* vn_w0     = (const float*)d_in[10];
    const float* vn_b0     = (const float*)d_in[11];
    const float* vn_w1     = (const float*)d_in[12];
    const float* vn_b1     = (const float*)d_in[13];
    const float* fc_W      = (const float*)d_in[14];
    const float* fc_b      = (const float*)d_in[15];
    const float* vn_init   = (const float*)d_in[16];
    const int*   ei        = (const int*)d_in[17];
    const int*   batch     = (const int*)d_in[18];
    float* out = (float*)d_out;

    const int SMEM = (64 * 128 + 128 * 128 + 128) * 4;   // 98816 B
    cudaFuncSetAttribute(gemm128, cudaFuncAttributeMaxDynamicSharedMemorySize, SMEM);

    float *p_h, *p_agg, *p_x, *p_sea, *p_deg, *p_counts, *p_vn, *p_p1, *p_pooled;
    cudaGetSymbolAddress((void**)&p_h, g_h);
    cudaGetSymbolAddress((void**)&p_agg, g_agg);
    cudaGetSymbolAddress((void**)&p_x, g_x);
    cudaGetSymbolAddress((void**)&p_sea, g_sea);
    cudaGetSymbolAddress((void**)&p_deg, g_deg);
    cudaGetSymbolAddress((void**)&p_counts, g_counts);
    cudaGetSymbolAddress((void**)&p_vn, g_vn);
    cudaGetSymbolAddress((void**)&p_p1, g_p1);
    cudaGetSymbolAddress((void**)&p_pooled, g_pooled);

    // layer-invariant precompute
    cudaMemsetAsync(p_sea, 0, (size_t)Nn * EDd * 4, 0);
    cudaMemsetAsync(p_deg, 0, (size_t)Nn * 4, 0);
    cudaMemsetAsync(p_counts, 0, (size_t)Bb * 4, 0);
    counts_kernel<<<(Nn + 255) / 256, 256>>>(batch);
    sea_deg_kernel<<<(Ee * 4) / 256, 256>>>(edge_attr, ei);
    vn_init_kernel<<<(Bb * Hh) / 256, 256>>>(vn_init);

    const int GRID_N = (Nn + 63) / 64;   // 782
    const int GRID_B = (Bb + 63) / 64;   // 4

    const float* xcur = x;
    for (int l = 0; l < Ll; l++) {
        // h = xcur @ nW + nb + vn[batch]
        gemm128<<<GRID_N, 256, SMEM>>>(xcur, node_W + l * Hh * Hh, node_b + l * Hh,
                                       p_h, Nn, M_VN, p_vn, batch, 0, 0);
        // agg = sea @ eW + deg*eb
        agg_init_kernel<<<(Nn + 1) / 2, 256>>>(edge_W + l * EDd * Hh, edge_b + l * Hh);
        // agg[dst] += h[src]
        scatter_kernel<<<(Ee * 32) / 256, 256>>>(ei);
        // t = relu(agg @ m1W + m1b)   (reuse h buffer)
        gemm128<<<GRID_N, 256, SMEM>>>(p_agg, mlp1_W + l * Hh * Hh, mlp1_b + l * Hh,
                                       p_h, Nn, M_RELU, 0, 0, 0, 0);
        // xn = relu(t @ m2W + m2b)
        gemm128<<<GRID_N, 256, SMEM>>>(p_h, mlp2_W + l * Hh * Hh, mlp2_b + l * Hh,
                                       p_x, Nn, M_RELU, 0, 0, 0, 0);
        // pooled = segsum(xn, batch)
        cudaMemsetAsync(p_pooled, 0, (size_t)Bb * Hh * 4, 0);
        pool_kernel<<<(Nn * 32 + 255) / 256, 256>>>(p_x, batch);
        if (l < Ll - 1) {
            // vn = vn + relu(relu((pooled/counts) @ w0 + b0) @ w1 + b1)
            gemm128<<<GRID_B, 256, SMEM>>>(p_pooled, vn_w0, vn_b0, p_p1, Bb,
                                           M_RELU | M_DIVC, 0, 0, 0, p_counts);
            gemm128<<<GRID_B, 256, SMEM>>>(p_p1, vn_w1, vn_b1, p_vn, Bb,
                                           M_RELU | M_RES, 0, 0, p_vn, 0);
        }
        xcur = p_x;
    }
    // out = (pooled/counts) @ fc_W + fc_b   (layer-5 pooled reused)
    gemm128<<<GRID_B, 256, SMEM>>>(p_pooled, fc_W, fc_b, out, Bb, M_DIVC, 0, 0, 0, p_counts);
}

// round 3
// speedup vs baseline: 1.2644x; 1.2644x over previous
#include <cuda_runtime.h>

#define Nn 50000
#define Ee 600000
#define Hh 128
#define EDd 16
#define Bb 256
#define Ll 5

// epilogue mode bits
#define M_RELU 1
#define M_VN   2
#define M_RES  4
#define M_DIVC 8

// ---------------- device scratch ----------------
__device__ float g_h[Nn * Hh];
__device__ float g_agg[Nn * Hh];
__device__ float g_x[Nn * Hh];
__device__ float g_sea[Nn * EDd];
__device__ float g_deg[Nn];
__device__ float g_counts[Bb];
__device__ float g_vn[Bb * Hh];
__device__ float g_pooled[Bb * Hh];

typedef unsigned long long u64;

__device__ __forceinline__ u64 pack2(float x) {
    u64 d; asm("mov.b64 %0, {%1, %1};" : "=l"(d) : "f"(x)); return d;
}
__device__ __forceinline__ u64 fma2(u64 a, u64 b, u64 c) {
    u64 d; asm("fma.rn.f32x2 %0, %1, %2, %3;" : "=l"(d) : "l"(a), "l"(b), "l"(c)); return d;
}
__device__ __forceinline__ void unpack2(u64 v, float& lo, float& hi) {
    asm("mov.b64 {%0, %1}, %2;" : "=f"(lo), "=f"(hi) : "l"(v));
}
__device__ __forceinline__ void red4(float* p, float4 v) {
    asm volatile("red.global.add.v4.f32 [%0], {%1, %2, %3, %4};"
                 :: "l"(p), "f"(v.x), "f"(v.y), "f"(v.z), "f"(v.w) : "memory");
}

// ================= shared MMA core: 128x128 tile, 256 threads, 8x8/thread =================
// As: [128 rows][128 k] row-major (float4 view As4), Ws: [128 k][128 cols].
__device__ __forceinline__ void mma_core(const float4* __restrict__ As4,
                                         const float* __restrict__ Ws,
                                         int tr, int tc, u64 acc[8][4])
{
#pragma unroll
    for (int r = 0; r < 8; r++)
#pragma unroll
        for (int j = 0; j < 4; j++) acc[r][j] = 0ull;

#pragma unroll 2
    for (int k0 = 0; k0 < 128; k0 += 4) {
        float4 av[8];
#pragma unroll
        for (int r = 0; r < 8; r++) av[r] = As4[(tr * 8 + r) * 32 + (k0 >> 2)];
#pragma unroll
        for (int kk = 0; kk < 4; kk++) {
            const ulonglong2* wp = (const ulonglong2*)(Ws + (k0 + kk) * 128 + tc * 8);
            ulonglong2 w01 = wp[0], w23 = wp[1];
#pragma unroll
            for (int r = 0; r < 8; r++) {
                float a = (kk == 0) ? av[r].x : (kk == 1) ? av[r].y
                        : (kk == 2) ? av[r].z : av[r].w;
                u64 a2 = pack2(a);
                acc[r][0] = fma2(a2, w01.x, acc[r][0]);
                acc[r][1] = fma2(a2, w01.y, acc[r][1]);
                acc[r][2] = fma2(a2, w23.x, acc[r][2]);
                acc[r][3] = fma2(a2, w23.y, acc[r][3]);
            }
        }
    }
}

__device__ __forceinline__ void load_W(const float* __restrict__ W, float* Ws, int tid) {
    const float4* W4  = (const float4*)W;
    float4*       Ws4 = (float4*)Ws;
#pragma unroll
    for (int i = 0; i < 16; i++) Ws4[tid + i * 256] = W4[tid + i * 256];
}

__device__ __forceinline__ void load_A(const float* __restrict__ A, float* As, int tid,
                                       int row0, int M, int mode,
                                       const float* __restrict__ counts)
{
    const float4* A4  = (const float4*)A;
    float4*       As4 = (float4*)As;
#pragma unroll
    for (int i = 0; i < 16; i++) {
        int fidx = tid + i * 256;
        int r = fidx >> 5, kq = fidx & 31;
        int gr = row0 + r;
        float4 v = make_float4(0.f, 0.f, 0.f, 0.f);
        if (gr < M) {
            v = A4[gr * 32 + kq];
            if (mode & M_DIVC) {
                float rc = 1.0f / fmaxf(counts[gr], 1.0f);
                v.x *= rc; v.y *= rc; v.z *= rc; v.w *= rc;
            }
        }
        As4[fidx] = v;
    }
}

// ================= single GEMM: C = epi(A @ W + b) =================
__global__ void __launch_bounds__(256) gemmS(
    const float* __restrict__ A, const float* __restrict__ W,
    const float* __restrict__ bias, float* __restrict__ C, int M, int mode,
    const float* __restrict__ vn, const int* __restrict__ batch,
    const float* __restrict__ resid, const float* __restrict__ counts)
{
    extern __shared__ float sm[];
    float* As = sm;
    float* Ws = sm + 16384;
    float* bs = sm + 32768;

    const int tid = threadIdx.x;
    const int row0 = blockIdx.x * 128;

    load_W(W, Ws, tid);
    if (tid < 128) bs[tid] = bias[tid];
    load_A(A, As, tid, row0, M, mode, counts);
    __syncthreads();

    const int tr = tid >> 4, tc = tid & 15;
    u64 acc[8][4];
    mma_core((const float4*)As, Ws, tr, tc, acc);

#pragma unroll
    for (int r = 0; r < 8; r++) {
        int gr = row0 + tr * 8 + r;
        if (gr >= M) continue;
        float o[8];
#pragma unroll
        for (int j = 0; j < 4; j++) unpack2(acc[r][j], o[2 * j], o[2 * j + 1]);
        const float* vrow = (mode & M_VN) ? (vn + (size_t)batch[gr] * 128) : (const float*)0;
#pragma unroll
        for (int c = 0; c < 8; c++) {
            int col = tc * 8 + c;
            float val = o[c] + bs[col];
            if (mode & M_VN)   val += vrow[col];
            if (mode & M_RELU) val = fmaxf(val, 0.0f);
            if (mode & M_RES)  val += resid[(size_t)gr * 128 + col];
            o[c] = val;
        }
        float4* Cp = (float4*)(C + (size_t)gr * 128 + tc * 8);
        Cp[0] = make_float4(o[0], o[1], o[2], o[3]);
        Cp[1] = make_float4(o[4], o[5], o[6], o[7]);
    }
}

// ================= fused double GEMM: C = epi2(epi1(A @ W1 + b1) @ W2 + b2) =================
__global__ void __launch_bounds__(256) gemmF(
    const float* __restrict__ A,
    const float* __restrict__ W1, const float* __restrict__ b1,
    const float* __restrict__ W2, const float* __restrict__ b2,
    float* __restrict__ C, int M, int mode1, int mode2,
    const float* __restrict__ resid, const float* __restrict__ counts)
{
    extern __shared__ float sm[];
    float* As  = sm;
    float* Ws  = sm + 16384;
    float* bs1 = sm + 32768;
    float* bs2 = sm + 32896;

    const int tid = threadIdx.x;
    const int row0 = blockIdx.x * 128;

    load_W(W1, Ws, tid);
    if (tid < 128) { bs1[tid] = b1[tid]; bs2[tid] = b2[tid]; }
    load_A(A, As, tid, row0, M, mode1, counts);
    __syncthreads();

    const int tr = tid >> 4, tc = tid & 15;
    u64 acc[8][4];
    mma_core((const float4*)As, Ws, tr, tc, acc);
    __syncthreads();   // all reads of As/Ws done

    // mid epilogue: t -> As ;  reload W2 -> Ws
#pragma unroll
    for (int r = 0; r < 8; r++) {
        float o[8];
#pragma unroll
        for (int j = 0; j < 4; j++) unpack2(acc[r][j], o[2 * j], o[2 * j + 1]);
#pragma unroll
        for (int c = 0; c < 8; c++) {
            float val = o[c] + bs1[tc * 8 + c];
            if (mode1 & M_RELU) val = fmaxf(val, 0.0f);
            o[c] = val;
        }
        float4* tp = (float4*)(As + (tr * 8 + r) * 128 + tc * 8);
        tp[0] = make_float4(o[0], o[1], o[2], o[3]);
        tp[1] = make_float4(o[4], o[5], o[6], o[7]);
    }
    load_W(W2, Ws, tid);
    __syncthreads();

    mma_core((const float4*)As, Ws, tr, tc, acc);

#pragma unroll
    for (int r = 0; r < 8; r++) {
        int gr = row0 + tr * 8 + r;
        if (gr >= M) continue;
        float o[8];
#pragma unroll
        for (int j = 0; j < 4; j++) unpack2(acc[r][j], o[2 * j], o[2 * j + 1]);
#pragma unroll
        for (int c = 0; c < 8; c++) {
            int col = tc * 8 + c;
            float val = o[c] + bs2[col];
            if (mode2 & M_RELU) val = fmaxf(val, 0.0f);
            if (mode2 & M_RES)  val += resid[(size_t)gr * 128 + col];
            o[c] = val;
        }
        float4* Cp = (float4*)(C + (size_t)gr * 128 + tc * 8);
        Cp[0] = make_float4(o[0], o[1], o[2], o[3]);
        Cp[1] = make_float4(o[4], o[5], o[6], o[7]);
    }
}

// ---------------- layer-invariant precompute ----------------
__global__ void counts_kernel(const int* __restrict__ batch) {
    int n = blockIdx.x * 256 + threadIdx.x;
    if (n < Nn) atomicAdd(&g_counts[batch[n]], 1.0f);
}

__global__ void sea_deg_kernel(const float* __restrict__ ea, const int* __restrict__ ei) {
    int gid = blockIdx.x * 256 + threadIdx.x;
    int e = gid >> 2, q = gid & 3;
    if (e >= Ee) return;
    int dst = ei[Ee + e];
    float4 v = ((const float4*)ea)[e * 4 + q];
    red4(&g_sea[dst * 16 + q * 4], v);
    if (q == 0) atomicAdd(&g_deg[dst], 1.0f);
}

__global__ void vn_init_kernel(const float* __restrict__ vi) {
    int i = blockIdx.x * 256 + threadIdx.x;
    if (i < Bb * Hh) g_vn[i] = vi[i & 127];
}

// ---------------- agg = sea @ eW + deg (x) eb  (32 rows / block) ----------------
__global__ void __launch_bounds__(256) agg_init_kernel(
    const float* __restrict__ eW, const float* __restrict__ eb)
{
    __shared__ float ws[EDd * Hh];
    __shared__ float ebs[Hh];
    __shared__ float srow[32 * EDd];
    __shared__ float sdeg[32];
    const int tid = threadIdx.x;
    const int r0 = blockIdx.x * 32;

    for (int i = tid; i < EDd * Hh; i += 256) ws[i] = eW[i];
    if (tid < Hh) ebs[tid] = eb[tid];
    for (int i = tid; i < 32 * EDd; i += 256) {
        int gr = r0 + (i >> 4);
        srow[i] = (gr < Nn) ? g_sea[(size_t)gr * 16 + (i & 15)] : 0.f;
    }
    if (tid < 32) { int gr = r0 + tid; sdeg[tid] = (gr < Nn) ? g_deg[gr] : 0.f; }
    __syncthreads();

    const int c = tid & 127;
#pragma unroll
    for (int it = 0; it < 16; it++) {
        int rl = it * 2 + (tid >> 7);
        int gr = r0 + rl;
        if (gr < Nn) {
            float acc = sdeg[rl] * ebs[c];
#pragma unroll
            for (int j = 0; j < 16; j++) acc = fmaf(srow[rl * 16 + j], ws[j * 128 + c], acc);
            g_agg[(size_t)gr * 128 + c] = acc;
        }
    }
}

// ---------------- agg[dst] += h[src]  (warp per edge) ----------------
__global__ void scatter_kernel(const int* __restrict__ ei) {
    int gid = blockIdx.x * 256 + threadIdx.x;
    int e = gid >> 5, q = gid & 31;
    if (e >= Ee) return;
    int src = ei[e], dst = ei[Ee + e];
    float4 v = ((const float4*)g_h)[src * 32 + q];
    red4(&g_agg[(size_t)dst * 128 + q * 4], v);
}

// ---------------- pooled[batch[n]] += xsrc[n]  (sorted batch: warp handles 64 nodes) ----------------
__global__ void pool_kernel(const float* __restrict__ xsrc, const int* __restrict__ batch) {
    int gid = blockIdx.x * 256 + threadIdx.x;
    int w = gid >> 5, lane = gid & 31;
    int n0 = w * 64;
    if (n0 >= Nn) return;
    const float4* x4 = (const float4*)xsrc;
    int cur = batch[n0];
    float4 acc = x4[(size_t)n0 * 32 + lane];
    int nend = (n0 + 64 < Nn) ? n0 + 64 : Nn;
    for (int n = n0 + 1; n < nend; n++) {
        int b = batch[n];
        float4 v = x4[(size_t)n * 32 + lane];
        if (b != cur) {
            red4(&g_pooled[cur * 128 + lane * 4], acc);
            acc = v; cur = b;
        } else {
            acc.x += v.x; acc.y += v.y; acc.z += v.z; acc.w += v.w;
        }
    }
    red4(&g_pooled[cur * 128 + lane * 4], acc);
}

// ---------------- launch ----------------
extern "C" void kernel_launch(void* const* d_in, const int* in_sizes, int n_in,
                              void* d_out, int out_size) {
    const float* x         = (const float*)d_in[0];
    const float* edge_attr = (const float*)d_in[1];
    const float* node_W    = (const float*)d_in[2];
    const float* node_b    = (const float*)d_in[3];
    const float* edge_W    = (const float*)d_in[4];
    const float* edge_b    = (const float*)d_in[5];
    const float* mlp1_W    = (const float*)d_in[6];
    const float* mlp1_b    = (const float*)d_in[7];
    const float* mlp2_W    = (const float*)d_in[8];
    const float* mlp2_b    = (const float*)d_in[9];
    const float* vn_w0     = (const float*)d_in[10];
    const float* vn_b0     = (const float*)d_in[11];
    const float* vn_w1     = (const float*)d_in[12];
    const float* vn_b1     = (const float*)d_in[13];
    const float* fc_W      = (const float*)d_in[14];
    const float* fc_b      = (const float*)d_in[15];
    const float* vn_init   = (const float*)d_in[16];
    const int*   ei        = (const int*)d_in[17];
    const int*   batch     = (const int*)d_in[18];
    float* out = (float*)d_out;

    const int SMEM_S = (16384 + 16384 + 128) * 4;
    const int SMEM_F = (16384 + 16384 + 256) * 4;
    cudaFuncSetAttribute(gemmS, cudaFuncAttributeMaxDynamicSharedMemorySize, SMEM_S);
    cudaFuncSetAttribute(gemmF, cudaFuncAttributeMaxDynamicSharedMemorySize, SMEM_F);

    float *p_h, *p_agg, *p_x, *p_sea, *p_deg, *p_counts, *p_vn, *p_pooled;
    cudaGetSymbolAddress((void**)&p_h, g_h);
    cudaGetSymbolAddress((void**)&p_agg, g_agg);
    cudaGetSymbolAddress((void**)&p_x, g_x);
    cudaGetSymbolAddress((void**)&p_sea, g_sea);
    cudaGetSymbolAddress((void**)&p_deg, g_deg);
    cudaGetSymbolAddress((void**)&p_counts, g_counts);
    cudaGetSymbolAddress((void**)&p_vn, g_vn);
    cudaGetSymbolAddress((void**)&p_pooled, g_pooled);

    // layer-invariant precompute
    cudaMemsetAsync(p_sea, 0, (size_t)Nn * EDd * 4, 0);
    cudaMemsetAsync(p_deg, 0, (size_t)Nn * 4, 0);
    cudaMemsetAsync(p_counts, 0, (size_t)Bb * 4, 0);
    counts_kernel<<<(Nn + 255) / 256, 256>>>(batch);
    sea_deg_kernel<<<(Ee * 4) / 256, 256>>>(edge_attr, ei);
    vn_init_kernel<<<(Bb * Hh) / 256, 256>>>(vn_init);

    const int GRID_N = (Nn + 127) / 128;                // 391
    const int GRID_B = (Bb + 127) / 128;                // 2
    const int GRID_POOL = ((Nn + 63) / 64 * 32 + 255) / 256;  // warps=782 -> 98 blocks

    const float* xcur = x;
    for (int l = 0; l < Ll; l++) {
        // h = xcur @ nW + nb + vn[batch]
        gemmS<<<GRID_N, 256, SMEM_S>>>(xcur, node_W + l * Hh * Hh, node_b + l * Hh,
                                       p_h, Nn, M_VN, p_vn, batch, 0, 0);
        // agg = sea @ eW + deg*eb
        agg_init_kernel<<<(Nn + 31) / 32, 256>>>(edge_W + l * EDd * Hh, edge_b + l * Hh);
        // agg[dst] += h[src]
        scatter_kernel<<<(Ee * 32) / 256, 256>>>(ei);
        // xn = relu(relu(agg @ m1W + m1b) @ m2W + m2b)
        gemmF<<<GRID_N, 256, SMEM_F>>>(p_agg, mlp1_W + l * Hh * Hh, mlp1_b + l * Hh,
                                       mlp2_W + l * Hh * Hh, mlp2_b + l * Hh,
                                       p_x, Nn, M_RELU, M_RELU, 0, 0);
        // pooled = segsum(xn, batch)
        cudaMemsetAsync(p_pooled, 0, (size_t)Bb * Hh * 4, 0);
        pool_kernel<<<GRID_POOL, 256>>>(p_x, batch);
        if (l < Ll - 1) {
            // vn += relu(relu((pooled/counts) @ w0 + b0) @ w1 + b1)
            gemmF<<<GRID_B, 256, SMEM_F>>>(p_pooled, vn_w0, vn_b0, vn_w1, vn_b1,
                                           p_vn, Bb, M_DIVC | M_RELU, M_RELU | M_RES,
                                           p_vn, p_counts);
        }
        xcur = p_x;
    }
    // out = (pooled/counts) @ fc_W + fc_b
    gemmS<<<GRID_B, 256, SMEM_S>>>(p_pooled, fc_W, fc_b, out, Bb, M_DIVC, 0, 0, 0, p_counts);
}

// round 6
// speedup vs baseline: 1.4290x; 1.1302x over previous
#include <cuda_runtime.h>

#define Nn 50000
#define Ee 600000
#define Hh 128
#define EDd 16
#define Bb 256
#define Ll 5

// epilogue mode bits
#define M_RELU 1
#define M_VN   2
#define M_RES  4
#define M_DIVC 8

// ---------------- device scratch ----------------
__device__ float g_h[Nn * Hh];
__device__ float g_agg[Nn * Hh];
__device__ float g_x[Nn * Hh];
__device__ float g_sea[Nn * EDd];
__device__ float g_counts[Bb];
__device__ float g_vn[Bb * Hh];
__device__ float g_pooled[Ll * Bb * Hh];
// CSR (layer-invariant, rebuilt each launch)
__device__ int g_hist[Nn];
__device__ int g_rowptr[Nn + 1];
__device__ int g_cursor[Nn];
__device__ int g_col[Ee];

typedef unsigned long long u64;

__device__ __forceinline__ u64 pack2(float x) {
    u64 d; asm("mov.b64 %0, {%1, %1};" : "=l"(d) : "f"(x)); return d;
}
__device__ __forceinline__ u64 fma2(u64 a, u64 b, u64 c) {
    u64 d; asm("fma.rn.f32x2 %0, %1, %2, %3;" : "=l"(d) : "l"(a), "l"(b), "l"(c)); return d;
}
__device__ __forceinline__ void unpack2(u64 v, float& lo, float& hi) {
    asm("mov.b64 {%0, %1}, %2;" : "=f"(lo), "=f"(hi) : "l"(v));
}
__device__ __forceinline__ void red4(float* p, float4 v) {
    asm volatile("red.global.add.v4.f32 [%0], {%1, %2, %3, %4};"
                 :: "l"(p), "f"(v.x), "f"(v.y), "f"(v.z), "f"(v.w) : "memory");
}

// ================= shared MMA core: 128x128 tile, 256 threads, 8x8/thread =================
__device__ __forceinline__ void mma_core(const float4* __restrict__ As4,
                                         const float* __restrict__ Ws,
                                         int tr, int tc, u64 acc[8][4])
{
#pragma unroll
    for (int r = 0; r < 8; r++)
#pragma unroll
        for (int j = 0; j < 4; j++) acc[r][j] = 0ull;

#pragma unroll 2
    for (int k0 = 0; k0 < 128; k0 += 4) {
        float4 av[8];
#pragma unroll
        for (int r = 0; r < 8; r++) av[r] = As4[(tr * 8 + r) * 32 + (k0 >> 2)];
#pragma unroll
        for (int kk = 0; kk < 4; kk++) {
            const ulonglong2* wp = (const ulonglong2*)(Ws + (k0 + kk) * 128 + tc * 8);
            ulonglong2 w01 = wp[0], w23 = wp[1];
#pragma unroll
            for (int r = 0; r < 8; r++) {
                float a = (kk == 0) ? av[r].x : (kk == 1) ? av[r].y
                        : (kk == 2) ? av[r].z : av[r].w;
                u64 a2 = pack2(a);
                acc[r][0] = fma2(a2, w01.x, acc[r][0]);
                acc[r][1] = fma2(a2, w01.y, acc[r][1]);
                acc[r][2] = fma2(a2, w23.x, acc[r][2]);
                acc[r][3] = fma2(a2, w23.y, acc[r][3]);
            }
        }
    }
}

__device__ __forceinline__ void load_W(const float* __restrict__ W, float* Ws, int tid) {
    const float4* W4  = (const float4*)W;
    float4*       Ws4 = (float4*)Ws;
#pragma unroll
    for (int i = 0; i < 16; i++) Ws4[tid + i * 256] = W4[tid + i * 256];
}

__device__ __forceinline__ void load_A(const float* __restrict__ A, float* As, int tid,
                                       int row0, int M, int mode,
                                       const float* __restrict__ counts)
{
    const float4* A4  = (const float4*)A;
    float4*       As4 = (float4*)As;
#pragma unroll
    for (int i = 0; i < 16; i++) {
        int fidx = tid + i * 256;
        int r = fidx >> 5, kq = fidx & 31;
        int gr = row0 + r;
        float4 v = make_float4(0.f, 0.f, 0.f, 0.f);
        if (gr < M) {
            v = A4[gr * 32 + kq];
            if (mode & M_DIVC) {
                float rc = 1.0f / fmaxf(counts[gr], 1.0f);
                v.x *= rc; v.y *= rc; v.z *= rc; v.w *= rc;
            }
        }
        As4[fidx] = v;
    }
}

// ================= single GEMM: C = epi(A @ W + b) =================
__global__ void __launch_bounds__(256) gemmS(
    const float* __restrict__ A, const float* __restrict__ W,
    const float* __restrict__ bias, float* __restrict__ C, int M, int mode,
    const float* __restrict__ vn, const int* __restrict__ batch,
    const float* __restrict__ resid, const float* __restrict__ counts)
{
    extern __shared__ float sm[];
    float* As = sm;
    float* Ws = sm + 16384;
    float* bs = sm + 32768;

    const int tid = threadIdx.x;
    const int row0 = blockIdx.x * 128;

    load_W(W, Ws, tid);
    if (tid < 128) bs[tid] = bias[tid];
    load_A(A, As, tid, row0, M, mode, counts);
    __syncthreads();

    const int tr = tid >> 4, tc = tid & 15;
    u64 acc[8][4];
    mma_core((const float4*)As, Ws, tr, tc, acc);

#pragma unroll
    for (int r = 0; r < 8; r++) {
        int gr = row0 + tr * 8 + r;
        if (gr >= M) continue;
        float o[8];
#pragma unroll
        for (int j = 0; j < 4; j++) unpack2(acc[r][j], o[2 * j], o[2 * j + 1]);
        const float* vrow = (mode & M_VN) ? (vn + (size_t)batch[gr] * 128) : (const float*)0;
#pragma unroll
        for (int c = 0; c < 8; c++) {
            int col = tc * 8 + c;
            float val = o[c] + bs[col];
            if (mode & M_VN)   val += vrow[col];
            if (mode & M_RELU) val = fmaxf(val, 0.0f);
            if (mode & M_RES)  val += resid[(size_t)gr * 128 + col];
            o[c] = val;
        }
        float4* Cp = (float4*)(C + (size_t)gr * 128 + tc * 8);
        Cp[0] = make_float4(o[0], o[1], o[2], o[3]);
        Cp[1] = make_float4(o[4], o[5], o[6], o[7]);
    }
}

// ================= fused double GEMM (both W preloaded): C = epi2(epi1(A@W1+b1)@W2+b2) =================
__global__ void __launch_bounds__(256) gemmF(
    const float* __restrict__ A,
    const float* __restrict__ W1, const float* __restrict__ b1,
    const float* __restrict__ W2, const float* __restrict__ b2,
    float* __restrict__ C, int M, int mode1, int mode2,
    const float* __restrict__ resid, const float* __restrict__ counts)
{
    extern __shared__ float sm[];
    float* As  = sm;
    float* Ws1 = sm + 16384;
    float* Ws2 = sm + 32768;
    float* bs1 = sm + 49152;
    float* bs2 = sm + 49280;

    const int tid = threadIdx.x;
    const int row0 = blockIdx.x * 128;

    load_W(W1, Ws1, tid);
    load_W(W2, Ws2, tid);
    if (tid < 128) { bs1[tid] = b1[tid]; bs2[tid] = b2[tid]; }
    load_A(A, As, tid, row0, M, mode1, counts);
    __syncthreads();

    const int tr = tid >> 4, tc = tid & 15;
    u64 acc[8][4];
    mma_core((const float4*)As, Ws1, tr, tc, acc);
    __syncthreads();   // all reads of As done before overwrite

    // mid epilogue: t -> As
#pragma unroll
    for (int r = 0; r < 8; r++) {
        float o[8];
#pragma unroll
        for (int j = 0; j < 4; j++) unpack2(acc[r][j], o[2 * j], o[2 * j + 1]);
#pragma unroll
        for (int c = 0; c < 8; c++) {
            float val = o[c] + bs1[tc * 8 + c];
            if (mode1 & M_RELU) val = fmaxf(val, 0.0f);
            o[c] = val;
        }
        float4* tp = (float4*)(As + (tr * 8 + r) * 128 + tc * 8);
        tp[0] = make_float4(o[0], o[1], o[2], o[3]);
        tp[1] = make_float4(o[4], o[5], o[6], o[7]);
    }
    __syncthreads();

    mma_core((const float4*)As, Ws2, tr, tc, acc);

#pragma unroll
    for (int r = 0; r < 8; r++) {
        int gr = row0 + tr * 8 + r;
        if (gr >= M) continue;
        float o[8];
#pragma unroll
        for (int j = 0; j < 4; j++) unpack2(acc[r][j], o[2 * j], o[2 * j + 1]);
#pragma unroll
        for (int c = 0; c < 8; c++) {
            int col = tc * 8 + c;
            float val = o[c] + bs2[col];
            if (mode2 & M_RELU) val = fmaxf(val, 0.0f);
            if (mode2 & M_RES)  val += resid[(size_t)gr * 128 + col];
            o[c] = val;
        }
        float4* Cp = (float4*)(C + (size_t)gr * 128 + tc * 8);
        Cp[0] = make_float4(o[0], o[1], o[2], o[3]);
        Cp[1] = make_float4(o[4], o[5], o[6], o[7]);
    }
}

// ---------------- layer-invariant precompute ----------------
__global__ void counts_kernel(const int* __restrict__ batch) {
    int n = blockIdx.x * 256 + threadIdx.x;
    if (n < Nn) atomicAdd(&g_counts[batch[n]], 1.0f);
}

__global__ void sea_kernel(const float* __restrict__ ea, const int* __restrict__ ei) {
    int gid = blockIdx.x * 256 + threadIdx.x;
    int e = gid >> 2, q = gid & 3;
    if (e >= Ee) return;
    int dst = ei[Ee + e];
    float4 v = ((const float4*)ea)[e * 4 + q];
    red4(&g_sea[dst * 16 + q * 4], v);
}

__global__ void vn_init_kernel(const float* __restrict__ vi) {
    int i = blockIdx.x * 256 + threadIdx.x;
    if (i < Bb * Hh) g_vn[i] = vi[i & 127];
}

// ---------------- CSR build (dst-sorted) ----------------
__global__ void hist_kernel(const int* __restrict__ ei) {
    int e = blockIdx.x * 256 + threadIdx.x;
    if (e < Ee) atomicAdd(&g_hist[ei[Ee + e]], 1);
}

__global__ void __launch_bounds__(1024) scan_kernel() {
    const int T = 1024;
    const int chunk = (Nn + T - 1) / T;   // 49
    int tid = threadIdx.x;
    int base = tid * chunk;
    int sum = 0;
    for (int i = 0; i < chunk; i++) {
        int idx = base + i;
        if (idx < Nn) sum += g_hist[idx];
    }
    __shared__ int ssum[T];
    ssum[tid] = sum;
    __syncthreads();
    for (int off = 1; off < T; off <<= 1) {
        int t = (tid >= off) ? ssum[tid - off] : 0;
        __syncthreads();
        ssum[tid] += t;
        __syncthreads();
    }
    int run = ssum[tid] - sum;   // exclusive prefix
    for (int i = 0; i < chunk; i++) {
        int idx = base + i;
        if (idx < Nn) {
            g_rowptr[idx] = run;
            g_cursor[idx] = run;
            run += g_hist[idx];
        }
    }
    if (tid == T - 1) g_rowptr[Nn] = run;
}

__global__ void fill_kernel(const int* __restrict__ ei) {
    int e = blockIdx.x * 256 + threadIdx.x;
    if (e >= Ee) return;
    int d = ei[Ee + e];
    int pos = atomicAdd(&g_cursor[d], 1);
    g_col[pos] = ei[e];
}

// ---------------- gather: agg[n] = deg*eb + sea[n]@eW + sum_{e->n} h[src] ----------------
// warp per node; lane handles 4 columns.
__global__ void __launch_bounds__(256) gather_kernel(
    const float* __restrict__ eW, const float* __restrict__ eb)
{
    __shared__ float ws[EDd * Hh];     // 8 KB
    __shared__ float ebs[Hh];
    const int tid = threadIdx.x;
    for (int i = tid; i < EDd * Hh; i += 256) ws[i] = eW[i];
    if (tid < Hh) ebs[tid] = eb[tid];
    __syncthreads();

    const int n = blockIdx.x * 8 + (tid >> 5);
    const int lane = tid & 31;
    if (n >= Nn) return;

    const int beg = g_rowptr[n], end = g_rowptr[n + 1];
    const float dg = (float)(end - beg);

    const float4* ebs4 = (const float4*)ebs;
    float4 eb4 = ebs4[lane];
    float4 acc = make_float4(dg * eb4.x, dg * eb4.y, dg * eb4.z, dg * eb4.w);

    // sea row broadcast via shfl
    float s = (lane < 16) ? g_sea[(size_t)n * 16 + lane] : 0.f;
    const float4* ws4 = (const float4*)ws;
#pragma unroll
    for (int j = 0; j < 16; j++) {
        float sj = __shfl_sync(0xffffffffu, s, j);
        float4 w = ws4[j * 32 + lane];
        acc.x = fmaf(sj, w.x, acc.x);
        acc.y = fmaf(sj, w.y, acc.y);
        acc.z = fmaf(sj, w.z, acc.z);
        acc.w = fmaf(sj, w.w, acc.w);
    }

    const float4* h4 = (const float4*)g_h;
    for (int e = beg; e < end; e++) {
        int src = g_col[e];
        float4 v = h4[(size_t)src * 32 + lane];
        acc.x += v.x; acc.y += v.y; acc.z += v.z; acc.w += v.w;
    }
    ((float4*)g_agg)[(size_t)n * 32 + lane] = acc;
}

// ---------------- pooled[batch[n]] += xsrc[n]  (sorted batch, warp handles 64 nodes) ----------------
__global__ void pool_kernel(const float* __restrict__ xsrc, const int* __restrict__ batch,
                            float* __restrict__ pooled) {
    int gid = blockIdx.x * 256 + threadIdx.x;
    int w = gid >> 5, lane = gid & 31;
    int n0 = w * 64;
    if (n0 >= Nn) return;
    const float4* x4 = (const float4*)xsrc;
    int cur = batch[n0];
    float4 acc = x4[(size_t)n0 * 32 + lane];
    int nend = (n0 + 64 < Nn) ? n0 + 64 : Nn;
    for (int n = n0 + 1; n < nend; n++) {
        int b = batch[n];
        float4 v = x4[(size_t)n * 32 + lane];
        if (b != cur) {
            red4(&pooled[cur * 128 + lane * 4], acc);
            acc = v; cur = b;
        } else {
            acc.x += v.x; acc.y += v.y; acc.z += v.z; acc.w += v.w;
        }
    }
    red4(&pooled[cur * 128 + lane * 4], acc);
}

// ---------------- launch ----------------
extern "C" void kernel_launch(void* const* d_in, const int* in_sizes, int n_in,
                              void* d_out, int out_size) {
    const float* x         = (const float*)d_in[0];
    const float* edge_attr = (const float*)d_in[1];
    const float* node_W    = (const float*)d_in[2];
    const float* node_b    = (const float*)d_in[3];
    const float* edge_W    = (const float*)d_in[4];
    const float* edge_b    = (const float*)d_in[5];
    const float* mlp1_W    = (const float*)d_in[6];
    const float* mlp1_b    = (const float*)d_in[7];
    const float* mlp2_W    = (const float*)d_in[8];
    const float* mlp2_b    = (const float*)d_in[9];
    const float* vn_w0     = (const float*)d_in[10];
    const float* vn_b0     = (const float*)d_in[11];
    const float* vn_w1     = (const float*)d_in[12];
    const float* vn_b1     = (const float*)d_in[13];
    const float* fc_W      = (const float*)d_in[14];
    const float* fc_b      = (const float*)d_in[15];
    const float* vn_init   = (const float*)d_in[16];
    const int*   ei        = (const int*)d_in[17];
    const int*   batch     = (const int*)d_in[18];
    float* out = (float*)d_out;

    const int SMEM_S = (16384 + 16384 + 128) * 4;            // 131584
    const int SMEM_F = (16384 + 16384 + 16384 + 256) * 4;    // 197632
    cudaFuncSetAttribute(gemmS, cudaFuncAttributeMaxDynamicSharedMemorySize, SMEM_S);
    cudaFuncSetAttribute(gemmF, cudaFuncAttributeMaxDynamicSharedMemorySize, SMEM_F);

    float *p_h, *p_agg, *p_x, *p_sea, *p_counts, *p_vn, *p_pooled;
    int *p_hist;
    cudaGetSymbolAddress((void**)&p_h, g_h);
    cudaGetSymbolAddress((void**)&p_agg, g_agg);
    cudaGetSymbolAddress((void**)&p_x, g_x);
    cudaGetSymbolAddress((void**)&p_sea, g_sea);
    cudaGetSymbolAddress((void**)&p_counts, g_counts);
    cudaGetSymbolAddress((void**)&p_vn, g_vn);
    cudaGetSymbolAddress((void**)&p_pooled, g_pooled);
    cudaGetSymbolAddress((void**)&p_hist, g_hist);

    // layer-invariant precompute
    cudaMemsetAsync(p_sea, 0, (size_t)Nn * EDd * 4, 0);
    cudaMemsetAsync(p_counts, 0, (size_t)Bb * 4, 0);
    cudaMemsetAsync(p_hist, 0, (size_t)Nn * 4, 0);
    cudaMemsetAsync(p_pooled, 0, (size_t)Ll * Bb * Hh * 4, 0);
    counts_kernel<<<(Nn + 255) / 256, 256>>>(batch);
    sea_kernel<<<(Ee * 4) / 256, 256>>>(edge_attr, ei);
    vn_init_kernel<<<(Bb * Hh) / 256, 256>>>(vn_init);
    hist_kernel<<<(Ee + 255) / 256, 256>>>(ei);
    scan_kernel<<<1, 1024>>>();
    fill_kernel<<<(Ee + 255) / 256, 256>>>(ei);

    const int GRID_N = (Nn + 127) / 128;                      // 391
    const int GRID_B = (Bb + 127) / 128;                      // 2
    const int GRID_G = (Nn + 7) / 8;                          // 6250
    const int GRID_POOL = ((Nn + 63) / 64 * 32 + 255) / 256;  // 98

    const float* xcur = x;
    for (int l = 0; l < Ll; l++) {
        float* pooled_l = p_pooled + (size_t)l * Bb * Hh;
        // h = xcur @ nW + nb + vn[batch]
        gemmS<<<GRID_N, 256, SMEM_S>>>(xcur, node_W + l * Hh * Hh, node_b + l * Hh,
                                       p_h, Nn, M_VN, p_vn, batch, 0, 0);
        // agg = deg*eb + sea@eW + sum h[src]   (CSR gather, no atomics)
        gather_kernel<<<GRID_G, 256>>>(edge_W + l * EDd * Hh, edge_b + l * Hh);
        // xn = relu(relu(agg @ m1W + m1b) @ m2W + m2b)
        gemmF<<<GRID_N, 256, SMEM_F>>>(p_agg, mlp1_W + l * Hh * Hh, mlp1_b + l * Hh,
                                       mlp2_W + l * Hh * Hh, mlp2_b + l * Hh,
                                       p_x, Nn, M_RELU, M_RELU, 0, 0);
        // pooled_l = segsum(xn, batch)
        pool_kernel<<<GRID_POOL, 256>>>(p_x, batch, pooled_l);
        if (l < Ll - 1) {
            // vn += relu(relu((pooled/counts) @ w0 + b0) @ w1 + b1)
            gemmF<<<GRID_B, 256, SMEM_F>>>(pooled_l, vn_w0, vn_b0, vn_w1, vn_b1,
                                           p_vn, Bb, M_DIVC | M_RELU, M_RELU | M_RES,
                                           p_vn, p_counts);
        }
        xcur = p_x;
    }
    // out = (pooled_4/counts) @ fc_W + fc_b
    gemmS<<<GRID_B, 256, SMEM_S>>>(p_pooled + (size_t)(Ll - 1) * Bb * Hh,
                                   fc_W, fc_b, out, Bb, M_DIVC, 0, 0, 0, p_counts);
}